// round 3
// baseline (speedup 1.0000x reference)
#include <cuda_runtime.h>
#include <cstdint>

// Problem constants (fixed shapes from reference)
#define B_   8
#define H_   8
#define S_   4096
#define D_   64
#define DM_  768
#define SM2  (S_ - 2)            // 4094
#define ROWS_TOTAL (B_ * SM2)    // 32752
#define CHUNKS 64
#define ROWS_PER_CHUNK 512       // 64*512 = 32768 >= 32752
#define DENOM ((float)(B_ * SM2))

// Scratch (static device globals: allocation-free per harness rules)
__device__ float g_scratch[H_][CHUNKS][2][D_ * D_];  // partial G / U sums (16 MB)
__device__ float g_G[H_][D_ * D_];
__device__ float g_U[H_][D_ * D_];
__device__ float g_NT[H_][D_ * D_];
__device__ float g_M[H_ * D_ * DM_];                 // fused new_trace @ W_out^T  (512 x 768)

// ---------------------------------------------------------------------------
// f32x2 packed helpers (FFMA2 — only reachable via PTX on sm_103a)
// ---------------------------------------------------------------------------
__device__ __forceinline__ unsigned long long dup_f32x2(float x) {
    unsigned long long r;
    asm("mov.b64 %0, {%1, %1};" : "=l"(r) : "r"(__float_as_uint(x)));
    return r;
}
__device__ __forceinline__ void fma_f32x2(unsigned long long& d,
                                          unsigned long long a,
                                          unsigned long long b) {
    asm("fma.rn.f32x2 %0, %1, %2, %0;" : "+l"(d) : "l"(a), "l"(b));
}

// ---------------------------------------------------------------------------
// Kernel 1: per-(head, chunk) partial Gram sums.
//   G[h] += q_hat q_hat^T   (q_hat = q / max(||q||, 1e-8))
//   U[h] += q v_shift^T     (v at i+2)
// Block = 256 threads, each owns a 4x4 tile of the 64x64 outputs (x2 matrices).
// ---------------------------------------------------------------------------
__global__ __launch_bounds__(256) void gram_partial(const float* __restrict__ Q,
                                                    const float* __restrict__ V) {
    const int c = blockIdx.x;   // chunk
    const int h = blockIdx.y;   // head
    const int t = threadIdx.x;

    __shared__ float sq[8][64];
    __shared__ float sv[8][64];
    __shared__ float sinv[8];

    const int p0 = (t >> 4) * 4;
    const int q0 = (t & 15) * 4;

    float aG[4][4];
    float aU[4][4];
#pragma unroll
    for (int i = 0; i < 4; ++i)
#pragma unroll
        for (int j = 0; j < 4; ++j) { aG[i][j] = 0.f; aU[i][j] = 0.f; }

    const int rbase = c * ROWS_PER_CHUNK;
    const int which = t >> 7;        // 0 -> q, 1 -> v
    const int li    = t & 127;
    const int lrow  = li >> 4;       // 0..7
    const int lf4   = li & 15;       // 0..15

    for (int it = 0; it < ROWS_PER_CHUNK / 8; ++it) {
        const int r8 = rbase + it * 8;
        // --- load 8 q-rows + 8 v-rows (float4 each), zero-fill out of range ---
        {
            const int r = r8 + lrow;
            float4 val = make_float4(0.f, 0.f, 0.f, 0.f);
            if (r < ROWS_TOTAL) {
                const int b = r / SM2;
                const int i = r - b * SM2;
                if (which == 0) {
                    val = *(const float4*)(Q + (((size_t)(b * H_ + h)) * S_ + i) * D_ + lf4 * 4);
                } else {
                    val = *(const float4*)(V + (((size_t)(b * H_ + h)) * S_ + (i + 2)) * D_ + lf4 * 4);
                }
            }
            float* dst = (which == 0) ? &sq[lrow][lf4 * 4] : &sv[lrow][lf4 * 4];
            *(float4*)dst = val;
        }
        __syncthreads();
        // --- inverse norms: warp w handles row w ---
        {
            const int w = t >> 5, lane = t & 31;
            float e0 = sq[w][lane], e1 = sq[w][lane + 32];
            float ss = e0 * e0 + e1 * e1;
#pragma unroll
            for (int off = 16; off > 0; off >>= 1)
                ss += __shfl_xor_sync(0xffffffffu, ss, off);
            if (lane == 0) sinv[w] = 1.0f / fmaxf(sqrtf(ss), 1e-8f);
        }
        __syncthreads();
        // --- accumulate 8 rows ---
#pragma unroll 4
        for (int r = 0; r < 8; ++r) {
            const float inv = sinv[r];
            float qp[4], qq[4], vv[4];
#pragma unroll
            for (int i = 0; i < 4; ++i) qp[i] = sq[r][p0 + i];
#pragma unroll
            for (int j = 0; j < 4; ++j) qq[j] = sq[r][q0 + j];
#pragma unroll
            for (int j = 0; j < 4; ++j) vv[j] = sv[r][q0 + j];
            float ap[4], bq[4];
#pragma unroll
            for (int i = 0; i < 4; ++i) ap[i] = qp[i] * inv;
#pragma unroll
            for (int j = 0; j < 4; ++j) bq[j] = qq[j] * inv;
#pragma unroll
            for (int i = 0; i < 4; ++i)
#pragma unroll
                for (int j = 0; j < 4; ++j) {
                    aG[i][j] += ap[i] * bq[j];
                    aU[i][j] += qp[i] * vv[j];
                }
        }
        __syncthreads();
    }

    float* oG = g_scratch[h][c][0];
    float* oU = g_scratch[h][c][1];
#pragma unroll
    for (int i = 0; i < 4; ++i) {
        *(float4*)&oG[(p0 + i) * 64 + q0] = *(float4*)&aG[i][0];
        *(float4*)&oU[(p0 + i) * 64 + q0] = *(float4*)&aU[i][0];
    }
}

// ---------------------------------------------------------------------------
// Kernel 2: deterministic reduction of chunk partials. grid (16, H), 256 thr.
// ---------------------------------------------------------------------------
__global__ __launch_bounds__(256) void reduce_gram() {
    const int h = blockIdx.y;
    const int e = blockIdx.x * 256 + threadIdx.x;   // 0..4095
    float sg = 0.f, su = 0.f;
    for (int c = 0; c < CHUNKS; ++c) {
        sg += g_scratch[h][c][0][e];
        su += g_scratch[h][c][1][e];
    }
    g_G[h][e] = sg;
    g_U[h][e] = su;
}

// ---------------------------------------------------------------------------
// Kernel 3: new_trace = 0.99*(trace - (G/denom)@trace) + 0.1*U/denom
// One block per head.
// ---------------------------------------------------------------------------
__global__ __launch_bounds__(256) void combine_trace(const float* __restrict__ trace) {
    const int h = blockIdx.x;
    const int t = threadIdx.x;
    __shared__ float Gs[4096];
    __shared__ float Ts[4096];
#pragma unroll
    for (int j = 0; j < 16; ++j) {
        Gs[t + 256 * j] = g_G[h][t + 256 * j];
        Ts[t + 256 * j] = trace[h * 4096 + t + 256 * j];
    }
    __syncthreads();
    const float invd = 1.0f / DENOM;
#pragma unroll
    for (int j = 0; j < 16; ++j) {
        const int e = t + 256 * j;
        const int p = e >> 6, q = e & 63;
        float acc = 0.f;
#pragma unroll 8
        for (int k = 0; k < 64; ++k)
            acc += Gs[p * 64 + k] * Ts[k * 64 + q];
        const float nt = 0.99f * (Ts[e] - acc * invd) + 0.1f * g_U[h][e] * invd;
        g_NT[h][e] = nt;
    }
}

// ---------------------------------------------------------------------------
// Kernel 4: Mbig[h*64+p][n] = sum_q nt[h][p][q] * W_out[n][h*64+q]
// grid (6, H): block covers 64 p-rows x 128 n-cols (two 64-col halves).
// ---------------------------------------------------------------------------
__global__ __launch_bounds__(256) void build_M(const float* __restrict__ W) {
    const int h  = blockIdx.y;
    const int n0 = blockIdx.x * 128;
    const int t  = threadIdx.x;
    __shared__ float nts[4096];
    __shared__ float Wt[64 * 64];
#pragma unroll
    for (int j = 0; j < 16; ++j) nts[t + 256 * j] = g_NT[h][t + 256 * j];
    for (int half = 0; half < 2; ++half) {
        __syncthreads();
#pragma unroll
        for (int j = 0; j < 4; ++j) {
            const int idx = t + 256 * j;       // 0..1023 float4 slots
            const int nn  = idx >> 4;
            const int f4  = idx & 15;
            float4 v = *(const float4*)(W + (size_t)(n0 + half * 64 + nn) * (H_ * D_) + h * 64 + f4 * 4);
            *(float4*)&Wt[nn * 64 + f4 * 4] = v;
        }
        __syncthreads();
#pragma unroll
        for (int j = 0; j < 16; ++j) {
            const int o  = t + 256 * j;        // 0..4095
            const int p  = o >> 6, nn = o & 63;
            float acc = 0.f;
#pragma unroll 8
            for (int q = 0; q < 64; ++q)
                acc += nts[p * 64 + q] * Wt[nn * 64 + q];
            g_M[(h * 64 + p) * DM_ + n0 + half * 64 + nn] = acc;
        }
    }
}

// ---------------------------------------------------------------------------
// Kernel 5: out[m][n] = sum_k Qaddr[m][k] * Mbig[k][n]
//   m = b*4096+s (A row is Q[b,h,s-1,:], zeros at s==0), k = h*64+d.
//   M=32768, N=768, K=512. BM=BN=128, BK=16, 256 threads, 8x8 per thread,
//   inner product via packed fma.rn.f32x2 (a = natural m-pairs, b = dup'd).
// ---------------------------------------------------------------------------
__global__ __launch_bounds__(256, 2) void out_gemm(const float* __restrict__ Q,
                                                   float* __restrict__ out) {
    __shared__ float As[16 * 132];   // transposed A tile, padded stride 132
    __shared__ float Bs[16 * 128];

    const int t = threadIdx.x;
    const int n_base = blockIdx.x * 128;
    const int m_base = blockIdx.y * 128;
    const int tx = t & 15;     // n
    const int ty = t >> 4;     // m

    unsigned long long acc[4][8];
#pragma unroll
    for (int i = 0; i < 4; ++i)
#pragma unroll
        for (int j = 0; j < 8; ++j) acc[i][j] = 0ull;

    for (int kt = 0; kt < 512; kt += 16) {
        // --- load A tile (128 m x 16 k), store transposed As[k][m] ---
#pragma unroll
        for (int l = 0; l < 2; ++l) {
            const int idx  = t + l * 256;     // 0..511 float4 slots
            const int mrow = idx >> 2;        // 0..127
            const int kq   = (idx & 3) * 4;   // 0,4,8,12
            const int m = m_base + mrow;
            const int s = m & 4095;
            const int b = m >> 12;
            const int k = kt + kq;
            const int hh = k >> 6, d = k & 63;
            float4 v = make_float4(0.f, 0.f, 0.f, 0.f);
            if (s > 0)
                v = *(const float4*)(Q + (((size_t)(b * H_ + hh)) * S_ + (s - 1)) * D_ + d);
            As[(kq + 0) * 132 + mrow] = v.x;
            As[(kq + 1) * 132 + mrow] = v.y;
            As[(kq + 2) * 132 + mrow] = v.z;
            As[(kq + 3) * 132 + mrow] = v.w;
        }
        // --- load B tile (16 k x 128 n) ---
#pragma unroll
        for (int l = 0; l < 2; ++l) {
            const int idx  = t + l * 256;     // 0..511 float4 slots
            const int krow = idx >> 5;        // 0..15
            const int nc   = (idx & 31) * 4;  // 0..124
            *(float4*)&Bs[krow * 128 + nc] =
                *(const float4*)(g_M + (size_t)(kt + krow) * DM_ + n_base + nc);
        }
        __syncthreads();

#pragma unroll
        for (int k = 0; k < 16; ++k) {
            unsigned long long a2[4];
#pragma unroll
            for (int i2 = 0; i2 < 4; ++i2)
                a2[i2] = *(const unsigned long long*)&As[k * 132 + ty * 8 + 2 * i2];
            const float4 b0 = *(const float4*)&Bs[k * 128 + tx * 8];
            const float4 b1 = *(const float4*)&Bs[k * 128 + tx * 8 + 4];
            unsigned long long bd[8];
            bd[0] = dup_f32x2(b0.x); bd[1] = dup_f32x2(b0.y);
            bd[2] = dup_f32x2(b0.z); bd[3] = dup_f32x2(b0.w);
            bd[4] = dup_f32x2(b1.x); bd[5] = dup_f32x2(b1.y);
            bd[6] = dup_f32x2(b1.z); bd[7] = dup_f32x2(b1.w);
#pragma unroll
            for (int i2 = 0; i2 < 4; ++i2)
#pragma unroll
                for (int j = 0; j < 8; ++j)
                    fma_f32x2(acc[i2][j], a2[i2], bd[j]);
        }
        __syncthreads();
    }

    // --- epilogue: acc[i2][j].lo -> row 2*i2, .hi -> row 2*i2+1 ---
#pragma unroll
    for (int i2 = 0; i2 < 4; ++i2) {
        float rlo[8], rhi[8];
#pragma unroll
        for (int j = 0; j < 8; ++j) {
            const unsigned long long v = acc[i2][j];
            rlo[j] = __uint_as_float((unsigned)(v & 0xffffffffu));
            rhi[j] = __uint_as_float((unsigned)(v >> 32));
        }
        const int mg = m_base + ty * 8 + 2 * i2;
        float* o0 = out + (size_t)mg * DM_ + n_base + tx * 8;
        float* o1 = o0 + DM_;
        *(float4*)(o0)     = make_float4(rlo[0], rlo[1], rlo[2], rlo[3]);
        *(float4*)(o0 + 4) = make_float4(rlo[4], rlo[5], rlo[6], rlo[7]);
        *(float4*)(o1)     = make_float4(rhi[0], rhi[1], rhi[2], rhi[3]);
        *(float4*)(o1 + 4) = make_float4(rhi[4], rhi[5], rhi[6], rhi[7]);
    }
}

// ---------------------------------------------------------------------------
extern "C" void kernel_launch(void* const* d_in, const int* in_sizes, int n_in,
                              void* d_out, int out_size) {
    const float* Q     = (const float*)d_in[0];
    const float* V     = (const float*)d_in[1];
    const float* trace = (const float*)d_in[2];
    const float* W     = (const float*)d_in[3];
    float* out = (float*)d_out;

    gram_partial<<<dim3(CHUNKS, H_), 256>>>(Q, V);
    reduce_gram<<<dim3(16, H_), 256>>>();
    combine_trace<<<H_, 256>>>(trace);
    build_M<<<dim3(6, H_), 256>>>(W);
    out_gemm<<<dim3(DM_ / 128, (B_ * S_) / 128), 256>>>(Q, out);
}

// round 5
// speedup vs baseline: 1.7987x; 1.7987x over previous
#include <cuda_runtime.h>
#include <cuda_bf16.h>
#include <cstdint>

// Problem constants
#define B_   8
#define H_   8
#define S_   4096
#define D_   64
#define DM_  768
#define SM2  (S_ - 2)            // 4094
#define ROWS_TOTAL (B_ * SM2)    // 32752
#define CHUNKS 64
#define ROWS_PER_CHUNK 512
#define DENOM ((float)(B_ * SM2))

#define MROWS (B_ * S_)          // 32768
#define KDIM  (H_ * D_)          // 512

// ---------------------------------------------------------------------------
// Static device scratch (allocation-free per harness rules)
// ---------------------------------------------------------------------------
__device__ float g_scratch[H_][CHUNKS][2][D_ * D_];
__device__ float g_G[H_][D_ * D_];
__device__ float g_U[H_][D_ * D_];
__device__ float g_NT[H_][D_ * D_];
__device__ __align__(16) __nv_bfloat16 g_Ahi[(size_t)MROWS * KDIM];
__device__ __align__(16) __nv_bfloat16 g_Alo[(size_t)MROWS * KDIM];
__device__ __align__(16) __nv_bfloat16 g_Bhi[(size_t)DM_ * KDIM];
__device__ __align__(16) __nv_bfloat16 g_Blo[(size_t)DM_ * KDIM];

// ---------------------------------------------------------------------------
// Helpers
// ---------------------------------------------------------------------------
__device__ __forceinline__ uint32_t smem_to_u32(const void* p) {
    uint32_t a;
    asm("{ .reg .u64 t; cvta.to.shared.u64 t, %1; cvt.u32.u64 %0, t; }" : "=r"(a) : "l"(p));
    return a;
}
__device__ __forceinline__ unsigned long long dup_f32x2(float x) {
    unsigned long long r;
    asm("mov.b64 %0, {%1, %1};" : "=l"(r) : "r"(__float_as_uint(x)));
    return r;
}
__device__ __forceinline__ void fma_f32x2(unsigned long long& d, unsigned long long a, unsigned long long b) {
    asm("fma.rn.f32x2 %0, %1, %2, %0;" : "+l"(d) : "l"(a), "l"(b));
}
__device__ __forceinline__ unsigned long long mul_f32x2(unsigned long long a, unsigned long long b) {
    unsigned long long r;
    asm("mul.rn.f32x2 %0, %1, %2;" : "=l"(r) : "l"(a), "l"(b));
    return r;
}
__device__ __forceinline__ void unpack_f32x2(float& lo, float& hi, unsigned long long v) {
    uint32_t l, h;
    asm("mov.b64 {%0, %1}, %2;" : "=r"(l), "=r"(h) : "l"(v));
    lo = __uint_as_float(l); hi = __uint_as_float(h);
}
__device__ __forceinline__ void mma_16816(float* c, const uint32_t* a, const uint32_t* b) {
    asm volatile(
        "mma.sync.aligned.m16n8k16.row.col.f32.bf16.bf16.f32 "
        "{%0,%1,%2,%3}, {%4,%5,%6,%7}, {%8,%9}, {%0,%1,%2,%3};"
        : "+f"(c[0]), "+f"(c[1]), "+f"(c[2]), "+f"(c[3])
        : "r"(a[0]), "r"(a[1]), "r"(a[2]), "r"(a[3]), "r"(b[0]), "r"(b[1]));
}
#define CP_ASYNC_16(smem_u32, gptr) \
    asm volatile("cp.async.cg.shared.global [%0], [%1], 16;" :: "r"(smem_u32), "l"(gptr))
#define CP_ASYNC_COMMIT() asm volatile("cp.async.commit_group;")
#define CP_ASYNC_WAIT(n)  asm volatile("cp.async.wait_group %0;" :: "n"(n))

// ---------------------------------------------------------------------------
// Kernel A1: Qaddr (shift-by-1) -> bf16 hi/lo split A matrix [m][k]
// ---------------------------------------------------------------------------
__global__ __launch_bounds__(256) void prepA(const float* __restrict__ Q) {
    const int idx = blockIdx.x * 256 + threadIdx.x;     // < 8*8*4095*16
    const int c4  = idx & 15;
    const int rst = idx >> 4;
    const int s   = rst % (S_ - 1);                     // 0..4094
    const int bh  = rst / (S_ - 1);
    const int h   = bh & 7;
    const int b   = bh >> 3;
    const float4 v = *(const float4*)(Q + (((size_t)(b * H_ + h)) * S_ + s) * D_ + c4 * 4);
    const size_t m = (size_t)b * S_ + s + 1;
    const size_t o = m * KDIM + h * 64 + c4 * 4;
    float x[4] = {v.x, v.y, v.z, v.w};
    __nv_bfloat16 hi[4], lo[4];
#pragma unroll
    for (int i = 0; i < 4; ++i) {
        hi[i] = __float2bfloat16_rn(x[i]);
        lo[i] = __float2bfloat16_rn(x[i] - __bfloat162float(hi[i]));
    }
    *(__nv_bfloat162*)(g_Ahi + o)     = __nv_bfloat162(hi[0], hi[1]);
    *(__nv_bfloat162*)(g_Ahi + o + 2) = __nv_bfloat162(hi[2], hi[3]);
    *(__nv_bfloat162*)(g_Alo + o)     = __nv_bfloat162(lo[0], lo[1]);
    *(__nv_bfloat162*)(g_Alo + o + 2) = __nv_bfloat162(lo[2], lo[3]);
}

__global__ __launch_bounds__(256) void zeroA() {
    const int idx = blockIdx.x * 256 + threadIdx.x;     // < 8*512
    const int b = idx >> 9, col = idx & 511;
    const size_t o = (size_t)b * S_ * KDIM + col;
    g_Ahi[o] = __float2bfloat16(0.f);
    g_Alo[o] = __float2bfloat16(0.f);
}

// ---------------------------------------------------------------------------
// Kernel 1: per-(head, chunk) partial Gram sums (f32x2 packed accumulation).
// ---------------------------------------------------------------------------
__global__ __launch_bounds__(256) void gram_partial(const float* __restrict__ Q,
                                                    const float* __restrict__ V) {
    const int c = blockIdx.x;
    const int h = blockIdx.y;
    const int t = threadIdx.x;

    __shared__ float sq[8][64];
    __shared__ float sv[8][64];
    __shared__ float sinv[8];

    const int p0 = (t >> 4) * 4;
    const int q0 = (t & 15) * 4;

    unsigned long long aG[4][2], aU[4][2];
#pragma unroll
    for (int i = 0; i < 4; ++i) { aG[i][0] = aG[i][1] = 0ull; aU[i][0] = aU[i][1] = 0ull; }

    const int rbase = c * ROWS_PER_CHUNK;
    const int which = t >> 7;
    const int li    = t & 127;
    const int lrow  = li >> 4;
    const int lf4   = li & 15;

    for (int it = 0; it < ROWS_PER_CHUNK / 8; ++it) {
        const int r8 = rbase + it * 8;
        {
            const int r = r8 + lrow;
            float4 val = make_float4(0.f, 0.f, 0.f, 0.f);
            if (r < ROWS_TOTAL) {
                const int b = r / SM2;
                const int i = r - b * SM2;
                if (which == 0)
                    val = *(const float4*)(Q + (((size_t)(b * H_ + h)) * S_ + i) * D_ + lf4 * 4);
                else
                    val = *(const float4*)(V + (((size_t)(b * H_ + h)) * S_ + (i + 2)) * D_ + lf4 * 4);
            }
            float* dst = (which == 0) ? &sq[lrow][lf4 * 4] : &sv[lrow][lf4 * 4];
            *(float4*)dst = val;
        }
        __syncthreads();
        {
            const int w = t >> 5, lane = t & 31;
            float e0 = sq[w][lane], e1 = sq[w][lane + 32];
            float ss = e0 * e0 + e1 * e1;
#pragma unroll
            for (int off = 16; off > 0; off >>= 1)
                ss += __shfl_xor_sync(0xffffffffu, ss, off);
            if (lane == 0) sinv[w] = 1.0f / fmaxf(sqrtf(ss), 1e-8f);
        }
        __syncthreads();
#pragma unroll 4
        for (int r = 0; r < 8; ++r) {
            const float inv  = sinv[r];
            const float inv2 = inv * inv;
            float qp[4];
#pragma unroll
            for (int i = 0; i < 4; ++i) qp[i] = sq[r][p0 + i];
            unsigned long long qqp[2], vvp[2];
            qqp[0] = *(const unsigned long long*)&sq[r][q0];
            qqp[1] = *(const unsigned long long*)&sq[r][q0 + 2];
            vvp[0] = *(const unsigned long long*)&sv[r][q0];
            vvp[1] = *(const unsigned long long*)&sv[r][q0 + 2];
            const unsigned long long d2 = dup_f32x2(inv2);
            unsigned long long gb[2];
            gb[0] = mul_f32x2(qqp[0], d2);
            gb[1] = mul_f32x2(qqp[1], d2);
            unsigned long long da[4];
#pragma unroll
            for (int i = 0; i < 4; ++i) da[i] = dup_f32x2(qp[i]);
#pragma unroll
            for (int i = 0; i < 4; ++i) {
                fma_f32x2(aG[i][0], da[i], gb[0]);
                fma_f32x2(aG[i][1], da[i], gb[1]);
                fma_f32x2(aU[i][0], da[i], vvp[0]);
                fma_f32x2(aU[i][1], da[i], vvp[1]);
            }
        }
        __syncthreads();
    }

    float* oG = g_scratch[h][c][0];
    float* oU = g_scratch[h][c][1];
#pragma unroll
    for (int i = 0; i < 4; ++i) {
        float4 vg, vu;
        unpack_f32x2(vg.x, vg.y, aG[i][0]);
        unpack_f32x2(vg.z, vg.w, aG[i][1]);
        unpack_f32x2(vu.x, vu.y, aU[i][0]);
        unpack_f32x2(vu.z, vu.w, aU[i][1]);
        *(float4*)&oG[(p0 + i) * 64 + q0] = vg;
        *(float4*)&oU[(p0 + i) * 64 + q0] = vu;
    }
}

// ---------------------------------------------------------------------------
// Kernel 2: reduce chunk partials.
// ---------------------------------------------------------------------------
__global__ __launch_bounds__(256) void reduce_gram() {
    const int h = blockIdx.y;
    const int e = blockIdx.x * 256 + threadIdx.x;
    float sg = 0.f, su = 0.f;
    for (int c = 0; c < CHUNKS; ++c) {
        sg += g_scratch[h][c][0][e];
        su += g_scratch[h][c][1][e];
    }
    g_G[h][e] = sg;
    g_U[h][e] = su;
}

// ---------------------------------------------------------------------------
// Kernel 3: new_trace = 0.99*(trace - (G/denom)@trace) + 0.1*U/denom
// ---------------------------------------------------------------------------
__global__ __launch_bounds__(256) void combine_trace(const float* __restrict__ trace) {
    const int h = blockIdx.x;
    const int t = threadIdx.x;
    __shared__ float Gs[4096];
    __shared__ float Ts[4096];
#pragma unroll
    for (int j = 0; j < 16; ++j) {
        Gs[t + 256 * j] = g_G[h][t + 256 * j];
        Ts[t + 256 * j] = trace[h * 4096 + t + 256 * j];
    }
    __syncthreads();
    const float invd = 1.0f / DENOM;
#pragma unroll
    for (int j = 0; j < 16; ++j) {
        const int e = t + 256 * j;
        const int p = e >> 6, q = e & 63;
        float acc = 0.f;
#pragma unroll 8
        for (int k = 0; k < 64; ++k)
            acc += Gs[p * 64 + k] * Ts[k * 64 + q];
        g_NT[h][e] = 0.99f * (Ts[e] - acc * invd) + 0.1f * g_U[h][e] * invd;
    }
}

// ---------------------------------------------------------------------------
// Kernel 4: B[n][h*64+p] = sum_q NT[h][p][q] * W[n][h*64+q] -> bf16 hi/lo.
// grid (12, 8), register-tiled 4x4.
// ---------------------------------------------------------------------------
__global__ __launch_bounds__(256) void build_M(const float* __restrict__ W) {
    const int h  = blockIdx.y;
    const int n0 = blockIdx.x * 64;
    const int t  = threadIdx.x;
    __shared__ float Wq[64][72];   // [q][n]
    __shared__ float Nq[64][72];   // [q][p]
#pragma unroll
    for (int j = 0; j < 4; ++j) {
        const int idx = t + j * 256;
        const int row = idx >> 4;
        const int q4  = (idx & 15) * 4;
        float4 wv = *(const float4*)(W + (size_t)(n0 + row) * KDIM + h * 64 + q4);
        Wq[q4 + 0][row] = wv.x; Wq[q4 + 1][row] = wv.y;
        Wq[q4 + 2][row] = wv.z; Wq[q4 + 3][row] = wv.w;
        float4 nv = *(const float4*)(&g_NT[h][row * 64 + q4]);
        Nq[q4 + 0][row] = nv.x; Nq[q4 + 1][row] = nv.y;
        Nq[q4 + 2][row] = nv.z; Nq[q4 + 3][row] = nv.w;
    }
    __syncthreads();
    const int tx = t & 15;     // p block
    const int ty = t >> 4;     // n block
    float acc[4][4];
#pragma unroll
    for (int i = 0; i < 4; ++i)
#pragma unroll
        for (int j = 0; j < 4; ++j) acc[i][j] = 0.f;
#pragma unroll 8
    for (int q = 0; q < 64; ++q) {
        const float4 wv = *(const float4*)&Wq[q][ty * 4];
        const float4 nv = *(const float4*)&Nq[q][tx * 4];
        const float w[4] = {wv.x, wv.y, wv.z, wv.w};
        const float nn[4] = {nv.x, nv.y, nv.z, nv.w};
#pragma unroll
        for (int i = 0; i < 4; ++i)
#pragma unroll
            for (int j = 0; j < 4; ++j)
                acc[i][j] += w[i] * nn[j];
    }
#pragma unroll
    for (int i = 0; i < 4; ++i) {
        const int n = n0 + ty * 4 + i;
#pragma unroll
        for (int j = 0; j < 4; ++j) {
            const int k = h * 64 + tx * 4 + j;
            const float x = acc[i][j];
            const __nv_bfloat16 hi = __float2bfloat16_rn(x);
            const __nv_bfloat16 lo = __float2bfloat16_rn(x - __bfloat162float(hi));
            g_Bhi[(size_t)n * KDIM + k] = hi;
            g_Blo[(size_t)n * KDIM + k] = lo;
        }
    }
}

// ---------------------------------------------------------------------------
// Kernel 5: out = A @ B^T via mma.sync bf16 (3-term split over 24 K-chunks).
// BM=BN=128, BK=64. 256 threads (8 warps, 2x4 warp grid, 64x32 warp tiles).
// Double-buffered cp.async. smem rows stride 72 bf16 (conflict-free frags).
// ---------------------------------------------------------------------------
#define STG_BYTES 36864                         // (128*72 + 128*72) * 2B
#define GEMM_SMEM (2 * STG_BYTES)               // 73728

__global__ __launch_bounds__(256, 2) void out_gemm_mma(float* __restrict__ out) {
    extern __shared__ __align__(16) char smem[];
    const int t = threadIdx.x;
    const int n_base = blockIdx.x * 128;
    const int m_base = blockIdx.y * 128;
    const uint32_t sbase = smem_to_u32(smem);

    const int lrow = t >> 3;        // 0..31 base row for loads (x4 iters)
    const int lc8  = t & 7;         // 16B chunk within 64-col row

    // chunk kc in 0..23:  k0 = (kc/3)*64 ; term = kc%3 (0:hi*hi 1:hi*lo 2:lo*hi)
    auto load_stage = [&](int kc, int stage) {
        const int k0 = (kc / 3) * 64;
        const int term = kc % 3;
        const __nv_bfloat16* Ag = (term == 2 ? g_Alo : g_Ahi);
        const __nv_bfloat16* Bg = (term == 1 ? g_Blo : g_Bhi);
        const uint32_t sa = sbase + stage * STG_BYTES;
        const uint32_t sb = sa + 128 * 144;
#pragma unroll
        for (int i = 0; i < 4; ++i) {
            const int row = lrow + i * 32;
            const __nv_bfloat16* g = Ag + (((size_t)(m_base + row)) << 9) + k0 + lc8 * 8;
            CP_ASYNC_16(sa + row * 144 + lc8 * 16, g);
        }
#pragma unroll
        for (int i = 0; i < 4; ++i) {
            const int row = lrow + i * 32;
            const __nv_bfloat16* g = Bg + (((size_t)(n_base + row)) << 9) + k0 + lc8 * 8;
            CP_ASYNC_16(sb + row * 144 + lc8 * 16, g);
        }
        CP_ASYNC_COMMIT();
    };

    const int wid = t >> 5, lane = t & 31;
    const int wm = wid >> 2;        // 0..1  (64 m-rows)
    const int wn = wid & 3;         // 0..3  (32 n-cols)
    const int fr = lane >> 2;       // 0..7
    const int fcb = (lane & 3) * 4; // k byte offset (2 bf16)

    float acc[4][4][4];
#pragma unroll
    for (int mi = 0; mi < 4; ++mi)
#pragma unroll
        for (int ni = 0; ni < 4; ++ni)
#pragma unroll
            for (int j = 0; j < 4; ++j) acc[mi][ni][j] = 0.f;

    load_stage(0, 0);
    for (int kc = 0; kc < 24; ++kc) {
        if (kc + 1 < 24) {
            load_stage(kc + 1, (kc + 1) & 1);
            CP_ASYNC_WAIT(1);
        } else {
            CP_ASYNC_WAIT(0);
        }
        __syncthreads();

        const char* As = smem + (kc & 1) * STG_BYTES;
        const char* Bs = As + 128 * 144;
#pragma unroll
        for (int kk = 0; kk < 4; ++kk) {
            const int cb = kk * 32 + fcb;        // k16-step byte offset
            uint32_t a[4][4];
#pragma unroll
            for (int mi = 0; mi < 4; ++mi) {
                const int r = wm * 64 + mi * 16 + fr;
                a[mi][0] = *(const uint32_t*)(As + r * 144 + cb);
                a[mi][1] = *(const uint32_t*)(As + (r + 8) * 144 + cb);
                a[mi][2] = *(const uint32_t*)(As + r * 144 + cb + 16);
                a[mi][3] = *(const uint32_t*)(As + (r + 8) * 144 + cb + 16);
            }
            uint32_t b[4][2];
#pragma unroll
            for (int ni = 0; ni < 4; ++ni) {
                const int n = wn * 32 + ni * 8 + fr;
                b[ni][0] = *(const uint32_t*)(Bs + n * 144 + cb);
                b[ni][1] = *(const uint32_t*)(Bs + n * 144 + cb + 16);
            }
#pragma unroll
            for (int mi = 0; mi < 4; ++mi)
#pragma unroll
                for (int ni = 0; ni < 4; ++ni)
                    mma_16816(acc[mi][ni], a[mi], b[ni]);
        }
        __syncthreads();
    }

    // Epilogue: c0,c1 -> (r, c..c+1); c2,c3 -> (r+8, c..c+1)
#pragma unroll
    for (int mi = 0; mi < 4; ++mi) {
        const int r = m_base + wm * 64 + mi * 16 + fr;
#pragma unroll
        for (int ni = 0; ni < 4; ++ni) {
            const int cg = n_base + wn * 32 + ni * 8 + (lane & 3) * 2;
            *(float2*)(out + (size_t)r * DM_ + cg) =
                make_float2(acc[mi][ni][0], acc[mi][ni][1]);
            *(float2*)(out + (size_t)(r + 8) * DM_ + cg) =
                make_float2(acc[mi][ni][2], acc[mi][ni][3]);
        }
    }
}

// ---------------------------------------------------------------------------
extern "C" void kernel_launch(void* const* d_in, const int* in_sizes, int n_in,
                              void* d_out, int out_size) {
    const float* Q     = (const float*)d_in[0];
    const float* V     = (const float*)d_in[1];
    const float* trace = (const float*)d_in[2];
    const float* W     = (const float*)d_in[3];
    float* out = (float*)d_out;

    static bool attr_set = false;
    if (!attr_set) {
        cudaFuncSetAttribute(out_gemm_mma, cudaFuncAttributeMaxDynamicSharedMemorySize, GEMM_SMEM);
        attr_set = true;
    }

    prepA<<<(B_ * H_ * (S_ - 1) * 16) / 256, 256>>>(Q);
    zeroA<<<(B_ * KDIM) / 256, 256>>>();
    gram_partial<<<dim3(CHUNKS, H_), 256>>>(Q, V);
    reduce_gram<<<dim3(16, H_), 256>>>();
    combine_trace<<<H_, 256>>>(trace);
    build_M<<<dim3(12, H_), 256>>>(W);
    out_gemm_mma<<<dim3(DM_ / 128, MROWS / 128), 256, GEMM_SMEM>>>(out);
}